// round 1
// baseline (speedup 1.0000x reference)
#include <cuda_runtime.h>
#include <math.h>

// ---------------------------------------------------------------------------
// CrossAttention — GB300 baseline (fp32 SIMT)
//
// Key algebraic facts exploited:
//   * softmax over j-axis of size 1  => a_o == 1  => o_o[l] = v_e (no q_o, k_e)
//   * out_o = broadcast_L( x_e @ (Wv_ego @ W_out_other) + b_out_other )
//   * all tensors share layout addr = (group*256 + c)*64 + n  (n = pixel)
//
// Pipeline (all on default stream, graph-capturable, allocation-free):
//   1. C_o   = Wv_ego @ W_out_other                       (tiny)
//   2. q_e   = ego  @ Wq_ego            -> g_qe
//   3. oo    = ego  @ C_o + b_out_other -> g_oo  (out_o before L-broadcast)
//   4. k_o   = other@ Wk_other          -> g_ko
//   5. v_o   = other@ Wv_other          -> g_vo
//   6. attn: per (pixel,head) 8-way softmax over agents   -> g_oe
//   7. out_e = g_oe @ W_out_ego + b_out_ego -> d_out[ego region]
//   8. broadcast g_oo over L             -> d_out[other region]
// ---------------------------------------------------------------------------

#define BM 128
#define BN 128
#define BK 8

// ---------------- scratch (device globals; no runtime allocation) ----------
__device__ float g_qe[16384ull * 256];        //  16 MB  q_e   [(b*32+k)][h*32+d][n]
__device__ float g_oo[16384ull * 256];        //  16 MB  out_o unique
__device__ float g_oe[16384ull * 256];        //  16 MB  merged o_e
__device__ float g_ko[2048ull * 256 * 64];    // 128 MB  k_o [(b*8+l)*32+k][hd][n]
__device__ float g_vo[2048ull * 256 * 64];    // 128 MB  v_o
__device__ float g_Co[256 * 256];             // combined Wv_ego @ W_out_other

// ---------------- C_o = Wv_ego @ W_out_other --------------------------------
__global__ void __launch_bounds__(256)
compute_Co(const float* __restrict__ Wqkv_ego,
           const float* __restrict__ Wout_other,
           float* __restrict__ Co)
{
    const int c = blockIdx.x;    // input channel (row of Wv_ego)
    const int o = threadIdx.x;   // output channel
    const float* wv = Wqkv_ego + (size_t)c * 768 + 512;  // Wv slice cols [512,768)
    float a0 = 0.f, a1 = 0.f, a2 = 0.f, a3 = 0.f;
    #pragma unroll 4
    for (int m = 0; m < 256; m += 4) {
        a0 += wv[m + 0] * Wout_other[(m + 0) * 256 + o];
        a1 += wv[m + 1] * Wout_other[(m + 1) * 256 + o];
        a2 += wv[m + 2] * Wout_other[(m + 2) * 256 + o];
        a3 += wv[m + 3] * Wout_other[(m + 3) * 256 + o];
    }
    Co[c * 256 + o] = (a0 + a1) + (a2 + a3);
}

// ---------------- generic SGEMM in the (group,c,n) layout -------------------
// A:  M x 256,   A[row, c]   at (row/64)*256*64 + c*64 + (row%64)
// B:  256 x 256 region, row-major with leading dim ldb (col offset pre-applied)
// C:  M x 256,   C[row, col] at (row/64)*256*64 + col*64 + (row%64)
// grid: (M/128, 2), 256 threads, 128x128 tile, 8x8 per-thread, double-buffered
__global__ void __launch_bounds__(256, 2)
sgemm_bkcn(const float* __restrict__ A,
           const float* __restrict__ B, int ldb,
           float* __restrict__ C,
           const float* __restrict__ bias)
{
    __shared__ float As[2][BK][BM];
    __shared__ float Bs[2][BK][BN];

    const int  tid  = threadIdx.x;
    const long row0 = (long)blockIdx.x * BM;   // multiple of 128 -> group aligned
    const int  col0 = blockIdx.y * BN;

    // ---- A staging: c = tid>>5 (0..7), 4 consecutive pixels per thread
    const int  a_c = tid >> 5;
    const int  a_r = (tid & 31) * 4;           // tile row (0..124), no 64-crossing
    const long arow = row0 + a_r;
    const float* Ap = A + ((size_t)(arow >> 6) * 256 + a_c) * 64 + (arow & 63);

    // ---- B staging: kk = tid>>5, 4 consecutive cols per thread
    const int  b_k = tid >> 5;
    const int  b_j = (tid & 31) * 4;
    const float* Bp = B + (size_t)b_k * ldb + col0 + b_j;

    float4 av = *(const float4*)Ap;
    float4 bv = *(const float4*)Bp;

    float acc[8][8];
    #pragma unroll
    for (int i = 0; i < 8; ++i)
        #pragma unroll
        for (int j = 0; j < 8; ++j) acc[i][j] = 0.f;

    const int row_m = (tid >> 4) * 8;   // 0..120, stays inside one 64-group
    const int col_n = (tid & 15) * 8;

    int buf = 0;
    #pragma unroll 1
    for (int kt = 0; kt < 32; ++kt) {
        *(float4*)&As[buf][a_c][a_r] = av;
        *(float4*)&Bs[buf][b_k][b_j] = bv;
        __syncthreads();
        if (kt < 31) {
            av = *(const float4*)(Ap + (size_t)(kt + 1) * 512);      // c += 8
            bv = *(const float4*)(Bp + (size_t)(kt + 1) * 8 * ldb);
        }
        #pragma unroll
        for (int kk = 0; kk < BK; ++kk) {
            float a0[8], b0[8];
            #pragma unroll
            for (int i = 0; i < 8; ++i) a0[i] = As[buf][kk][row_m + i];
            #pragma unroll
            for (int j = 0; j < 8; ++j) b0[j] = Bs[buf][kk][col_n + j];
            #pragma unroll
            for (int i = 0; i < 8; ++i)
                #pragma unroll
                for (int j = 0; j < 8; ++j)
                    acc[i][j] += a0[i] * b0[j];
        }
        buf ^= 1;
    }

    // ---- epilogue: C[(group*256 + col)*64 + n], float4 along n
    const size_t group = (size_t)(row0 + row_m) >> 6;
    const int    n0    = (int)((row0 + row_m) & 63);
    #pragma unroll
    for (int j = 0; j < 8; ++j) {
        const int col = col0 + col_n + j;
        const float bj = bias ? __ldg(bias + col) : 0.f;
        float* cp = C + (group * 256 + col) * 64 + n0;
        float4 v0 = make_float4(acc[0][j] + bj, acc[1][j] + bj,
                                acc[2][j] + bj, acc[3][j] + bj);
        float4 v1 = make_float4(acc[4][j] + bj, acc[5][j] + bj,
                                acc[6][j] + bj, acc[7][j] + bj);
        *(float4*)cp       = v0;
        *(float4*)(cp + 4) = v1;
    }
}

// ---------------- attention: per (pixel, head), softmax over 8 agents -------
// grid = B*K*2 = 512 blocks, 256 threads. thread -> (head, pixel n).
// Warp lanes are consecutive n  => every global access is a coalesced 128B line.
__global__ void __launch_bounds__(256)
attn_kernel(const float* __restrict__ qe, const float* __restrict__ ko,
            const float* __restrict__ vo, float* __restrict__ oe)
{
    const int ge = blockIdx.x >> 1;              // b*32 + k
    const int b  = ge >> 5;
    const int k  = ge & 31;
    const int h  = ((blockIdx.x & 1) << 2) + (threadIdx.x >> 6);
    const int n  = threadIdx.x & 63;
    const float scale = 0.1767766952966369f;     // 32^-0.5

    const float* qp = qe + ((size_t)ge * 256 + h * 32) * 64 + n;
    float q[32];
    #pragma unroll
    for (int d = 0; d < 32; ++d) q[d] = qp[d * 64];

    float logit[8];
    #pragma unroll
    for (int j = 0; j < 8; ++j) {
        const size_t go = (size_t)(b * 8 + j) * 32 + k;
        const float* kp = ko + (go * 256 + h * 32) * 64 + n;
        float s = 0.f;
        #pragma unroll
        for (int d = 0; d < 32; ++d) s += q[d] * kp[d * 64];
        logit[j] = s * scale;
    }

    float m = logit[0];
    #pragma unroll
    for (int j = 1; j < 8; ++j) m = fmaxf(m, logit[j]);
    float denom = 0.f;
    #pragma unroll
    for (int j = 0; j < 8; ++j) { logit[j] = expf(logit[j] - m); denom += logit[j]; }
    const float inv = 1.f / denom;

    float o[32];
    #pragma unroll
    for (int d = 0; d < 32; ++d) o[d] = 0.f;
    #pragma unroll
    for (int j = 0; j < 8; ++j) {
        const float a = logit[j] * inv;
        const float* vp = vo + ((size_t)(b * 8 + j) * 32 + k) * 16384 + (h * 32) * 64 + n;
        #pragma unroll
        for (int d = 0; d < 32; ++d) o[d] += a * vp[d * 64];
    }

    float* op = oe + ((size_t)ge * 256 + h * 32) * 64 + n;
    #pragma unroll
    for (int d = 0; d < 32; ++d) op[d * 64] = o[d];
}

// ---------------- out_o broadcast over L ------------------------------------
__global__ void __launch_bounds__(256)
bcast_oo(const float* __restrict__ oo, float* __restrict__ outO)
{
    const int ge = blockIdx.x;       // b*32 + k
    const int b  = ge >> 5;
    const int k  = ge & 31;
    const float4* src = (const float4*)(oo + (size_t)ge * 16384);
    float4* dst[8];
    #pragma unroll
    for (int l = 0; l < 8; ++l)
        dst[l] = (float4*)(outO + (size_t)((b * 8 + l) * 32 + k) * 16384);
    for (int i = threadIdx.x; i < 4096; i += 256) {
        const float4 v = src[i];
        #pragma unroll
        for (int l = 0; l < 8; ++l) dst[l][i] = v;
    }
}

// ---------------- launcher ---------------------------------------------------
extern "C" void kernel_launch(void* const* d_in, const int* in_sizes, int n_in,
                              void* d_out, int out_size)
{
    const float* ego    = (const float*)d_in[0];  // [B,K,256,8,8]
    const float* oth    = (const float*)d_in[1];  // [B,L,K,256,8,8]
    const float* Wqkv_e = (const float*)d_in[2];  // [256,768]
    const float* Wqkv_o = (const float*)d_in[3];  // [256,768]
    const float* Wout_e = (const float*)d_in[4];  // [256,256]
    const float* bout_e = (const float*)d_in[5];  // [256]
    const float* Wout_o = (const float*)d_in[6];  // [256,256]
    const float* bout_o = (const float*)d_in[7];  // [256]

    float* outE = (float*)d_out;                  // [B,K,256,8,8]
    float* outO = outE + 16384ull * 256;          // [B,L,K,256,8,8]

    float *qe, *oo, *oe, *ko, *vo, *Co;
    cudaGetSymbolAddress((void**)&qe, g_qe);
    cudaGetSymbolAddress((void**)&oo, g_oo);
    cudaGetSymbolAddress((void**)&oe, g_oe);
    cudaGetSymbolAddress((void**)&ko, g_ko);
    cudaGetSymbolAddress((void**)&vo, g_vo);
    cudaGetSymbolAddress((void**)&Co, g_Co);

    // 1. combined out_o weight
    compute_Co<<<256, 256>>>(Wqkv_e, Wout_o, Co);

    // 2. q_e = ego @ Wq_ego   (cols 0..255 of W_qkv_ego)
    sgemm_bkcn<<<dim3(128, 2), 256>>>(ego, Wqkv_e, 768, qe, nullptr);

    // 3. out_o unique = ego @ C_o + b_out_other
    sgemm_bkcn<<<dim3(128, 2), 256>>>(ego, Co, 256, oo, bout_o);

    // 4. k_o = other @ Wk_other  (cols 256..511)
    sgemm_bkcn<<<dim3(1024, 2), 256>>>(oth, Wqkv_o + 256, 768, ko, nullptr);

    // 5. v_o = other @ Wv_other  (cols 512..767)
    sgemm_bkcn<<<dim3(1024, 2), 256>>>(oth, Wqkv_o + 512, 768, vo, nullptr);

    // 6. attention
    attn_kernel<<<512, 256>>>(qe, ko, vo, oe);

    // 7. out_e = o_e @ W_out_ego + b_out_ego
    sgemm_bkcn<<<dim3(128, 2), 256>>>(oe, Wout_e, 256, outE, bout_e);

    // 8. broadcast out_o over L
    bcast_oo<<<256, 256>>>(oo, outO);
}

// round 3
// speedup vs baseline: 2.1393x; 2.1393x over previous
#include <cuda_runtime.h>
#include <cuda_bf16.h>
#include <cstdint>
#include <math.h>

// ===========================================================================
// CrossAttention — mma.sync bf16-split implementation (tcgen05 unavailable:
// harness PTX target is compute_103, no 'a' features).
//
// Algebra (validated R1, rel_err 5e-7):
//   * a_o == 1  =>  out_o = broadcast_L( ego @ (Wv_ego @ W_out_other) + b_o )
//   * all activations share layout  addr = (group*256 + c)*64 + n
// GEMMs: D = A(fp32, bf16-split on the fly) @ W(bf16-split, pre-transformed),
// 3 mma.sync per fragment pair: Ah*Bh + Al*Bh + Ah*Bl  (error ~2^-16).
// ===========================================================================

__device__ __forceinline__ uint32_t smem_u32(const void* p) {
    uint32_t a;
    asm("{ .reg .u64 t; cvta.to.shared.u64 t, %1; cvt.u32.u64 %0, t; }"
        : "=r"(a) : "l"(p));
    return a;
}

__device__ __forceinline__ void ldmx4t(uint32_t& r0, uint32_t& r1,
                                       uint32_t& r2, uint32_t& r3, uint32_t addr) {
    asm volatile("ldmatrix.sync.aligned.m8n8.x4.trans.shared.b16 {%0,%1,%2,%3}, [%4];"
                 : "=r"(r0), "=r"(r1), "=r"(r2), "=r"(r3) : "r"(addr));
}

__device__ __forceinline__ void mma_bf16(float* c, const uint32_t* a, const uint32_t* b) {
    asm volatile("mma.sync.aligned.m16n8k16.row.col.f32.bf16.bf16.f32 "
                 "{%0,%1,%2,%3}, {%4,%5,%6,%7}, {%8,%9}, {%0,%1,%2,%3};"
                 : "+f"(c[0]), "+f"(c[1]), "+f"(c[2]), "+f"(c[3])
                 : "r"(a[0]), "r"(a[1]), "r"(a[2]), "r"(a[3]),
                   "r"(b[0]), "r"(b[1]));
}

#define CP_ASYNC16(dst, src) \
    asm volatile("cp.async.cg.shared.global [%0], [%1], 16;" :: "r"(dst), "l"(src))
#define CP_COMMIT() asm volatile("cp.async.commit_group;" ::: "memory")
#define CP_WAIT0()  asm volatile("cp.async.wait_group 0;" ::: "memory")

// ---------------- scratch (device globals) ----------------------------------
__device__ float g_qe[16384ull * 256];
__device__ float g_oo[16384ull * 256];
__device__ float g_oe[16384ull * 256];
__device__ float g_ko[2048ull * 256 * 64];
__device__ float g_vo[2048ull * 256 * 64];
__device__ float g_Co[256 * 256];
// bf16 split weights, layout [c][col] (c = input channel), 256x256 each
__device__ __align__(16) unsigned short g_wq_h[65536], g_wq_l[65536];
__device__ __align__(16) unsigned short g_wk_h[65536], g_wk_l[65536];
__device__ __align__(16) unsigned short g_wv_h[65536], g_wv_l[65536];
__device__ __align__(16) unsigned short g_we_h[65536], g_we_l[65536];
__device__ __align__(16) unsigned short g_co_h[65536], g_co_l[65536];

// ---------------- C_o = Wv_ego @ W_out_other ---------------------------------
__global__ void __launch_bounds__(256)
compute_Co(const float* __restrict__ Wqkv_ego,
           const float* __restrict__ Wout_other,
           float* __restrict__ Co)
{
    const int c = blockIdx.x;
    const int o = threadIdx.x;
    const float* wv = Wqkv_ego + (size_t)c * 768 + 512;
    float a0 = 0.f, a1 = 0.f, a2 = 0.f, a3 = 0.f;
    #pragma unroll 4
    for (int m = 0; m < 256; m += 4) {
        a0 += wv[m + 0] * Wout_other[(m + 0) * 256 + o];
        a1 += wv[m + 1] * Wout_other[(m + 1) * 256 + o];
        a2 += wv[m + 2] * Wout_other[(m + 2) * 256 + o];
        a3 += wv[m + 3] * Wout_other[(m + 3) * 256 + o];
    }
    Co[c * 256 + o] = (a0 + a1) + (a2 + a3);
}

// ---------------- weight split: fp32 [c][ld] slice -> bf16 hi/lo [c][256] ---
__global__ void __launch_bounds__(256)
wsplit(const float* __restrict__ src, int ld, int col0,
       unsigned short* __restrict__ hi, unsigned short* __restrict__ lo)
{
    const int c = blockIdx.x, col = threadIdx.x;
    const float v = src[(size_t)c * ld + col0 + col];
    const __nv_bfloat16 h = __float2bfloat16(v);
    const __nv_bfloat16 l = __float2bfloat16(v - __bfloat162float(h));
    hi[c * 256 + col] = __bfloat16_as_ushort(h);
    lo[c * 256 + col] = __bfloat16_as_ushort(l);
}

// ---------------- bf16-split GEMM -------------------------------------------
// C[row,col] = sum_c A[row,c] * W[c,col] (+bias), rows = pixels in the
// (group, c, n) layout: A elem (row,c) at (g0+row/64)*16384 + c*64 + row%64.
// Block tile 128x128, K = 256 in 8 chunks of 32, double-buffered smem.
// smem per buf (bf16, rows padded to 136): Ah[32][136], Al, Bh[32][136], Bl.
#define BUF_BYTES 34816
#define GEMM_SMEM (2 * BUF_BYTES)

__global__ void __launch_bounds__(256, 2)
bf16_gemm(const float* __restrict__ A,
          const unsigned short* __restrict__ Bh,
          const unsigned short* __restrict__ Bl,
          float* __restrict__ C,
          const float* __restrict__ bias)
{
    extern __shared__ char smem[];
    const uint32_t sbase = smem_u32(smem);
    const int tid = threadIdx.x, lane = tid & 31, wid = tid >> 5;
    const int wm = wid & 1, wn = wid >> 1;          // 2 x 4 warp grid
    const size_t g0 = (size_t)blockIdx.x * 2;       // two 64-pixel groups
    const int bcol0 = blockIdx.y * 128;

    // ---- staging geometry
    const int sm = (tid & 31) * 4;                  // 4 consecutive pixels
    const int sk = tid >> 5;                        // base k row (0..7)
    const float* Abase = A + (g0 + (size_t)(sm >> 6)) * 16384 + (sm & 63);

    // ---- ldmatrix lane offsets (derived from PTX ISA fragment tables)
    const int a_k = (lane & 7) + ((lane >> 4) << 3);
    const int a_m = ((lane >> 3) & 1) << 3;
    const int b_k = (lane & 7) + (((lane >> 3) & 1) << 3);
    const int b_n = (lane >> 4) << 3;

    float acc[4][4][4];
    #pragma unroll
    for (int i = 0; i < 4; ++i)
        #pragma unroll
        for (int j = 0; j < 4; ++j)
            #pragma unroll
            for (int r = 0; r < 4; ++r) acc[i][j][r] = 0.f;

    float4 areg[4];

    // ================= prologue: stage chunk 0 into buf 0 ==================
    #pragma unroll
    for (int it = 0; it < 4; ++it)
        areg[it] = *(const float4*)(Abase + (size_t)(sk + it * 8) * 64);
    #pragma unroll
    for (int it = 0; it < 4; ++it) {
        const int s = tid + (it << 8);
        const int sel = s >> 9, row = (s >> 4) & 31, seg = s & 15;
        const unsigned short* src = (sel ? Bl : Bh)
            + (size_t)row * 256 + bcol0 + seg * 8;
        CP_ASYNC16(sbase + 17408 + sel * 8704 + row * 272 + seg * 16, src);
    }
    CP_COMMIT();
    #pragma unroll
    for (int it = 0; it < 4; ++it) {
        const int k = sk + it * 8;
        const float4 v = areg[it];
        __nv_bfloat162 h01 = __floats2bfloat162_rn(v.x, v.y);
        __nv_bfloat162 h23 = __floats2bfloat162_rn(v.z, v.w);
        float2 f01 = __bfloat1622float2(h01);
        float2 f23 = __bfloat1622float2(h23);
        __nv_bfloat162 l01 = __floats2bfloat162_rn(v.x - f01.x, v.y - f01.y);
        __nv_bfloat162 l23 = __floats2bfloat162_rn(v.z - f23.x, v.w - f23.y);
        char* ph = smem + (size_t)k * 272 + sm * 2;
        *(__nv_bfloat162*)(ph)     = h01;
        *(__nv_bfloat162*)(ph + 4) = h23;
        char* pl = ph + 8704;
        *(__nv_bfloat162*)(pl)     = l01;
        *(__nv_bfloat162*)(pl + 4) = l23;
    }
    CP_WAIT0();
    __syncthreads();

    // ================= main loop ===========================================
    int buf = 0;
    #pragma unroll 1
    for (int ch = 0; ch < 8; ++ch) {
        const int nc0 = (ch + 1) << 5;
        if (ch < 7) {
            #pragma unroll
            for (int it = 0; it < 4; ++it)
                areg[it] = *(const float4*)(Abase + (size_t)(nc0 + sk + it * 8) * 64);
            const uint32_t nb = sbase + (buf ^ 1) * BUF_BYTES;
            #pragma unroll
            for (int it = 0; it < 4; ++it) {
                const int s = tid + (it << 8);
                const int sel = s >> 9, row = (s >> 4) & 31, seg = s & 15;
                const unsigned short* src = (sel ? Bl : Bh)
                    + (size_t)(nc0 + row) * 256 + bcol0 + seg * 8;
                CP_ASYNC16(nb + 17408 + sel * 8704 + row * 272 + seg * 16, src);
            }
            CP_COMMIT();
        }

        // ---- compute chunk from buf
        {
            const uint32_t Ab = sbase + buf * BUF_BYTES;
            const uint32_t Bb = Ab + 17408;
            #pragma unroll
            for (int s = 0; s < 2; ++s) {
                const int klo = s << 4;
                uint32_t bh[4][2], ah[4][4];
                #pragma unroll
                for (int nbj = 0; nbj < 2; ++nbj)
                    ldmx4t(bh[2 * nbj][0], bh[2 * nbj][1],
                           bh[2 * nbj + 1][0], bh[2 * nbj + 1][1],
                           Bb + ((klo + b_k) * 136 + wn * 32 + nbj * 16 + b_n) * 2);
                #pragma unroll
                for (int mi = 0; mi < 4; ++mi)
                    ldmx4t(ah[mi][0], ah[mi][1], ah[mi][2], ah[mi][3],
                           Ab + ((klo + a_k) * 136 + wm * 64 + mi * 16 + a_m) * 2);
                #pragma unroll
                for (int mi = 0; mi < 4; ++mi)
                    #pragma unroll
                    for (int nj = 0; nj < 4; ++nj)
                        mma_bf16(acc[mi][nj], ah[mi], bh[nj]);
                // Al * Bh
                {
                    uint32_t al[4][4];
                    #pragma unroll
                    for (int mi = 0; mi < 4; ++mi)
                        ldmx4t(al[mi][0], al[mi][1], al[mi][2], al[mi][3],
                               Ab + 8704 + ((klo + a_k) * 136 + wm * 64 + mi * 16 + a_m) * 2);
                    #pragma unroll
                    for (int mi = 0; mi < 4; ++mi)
                        #pragma unroll
                        for (int nj = 0; nj < 4; ++nj)
                            mma_bf16(acc[mi][nj], al[mi], bh[nj]);
                }
                // Ah * Bl
                {
                    uint32_t bl[4][2];
                    #pragma unroll
                    for (int nbj = 0; nbj < 2; ++nbj)
                        ldmx4t(bl[2 * nbj][0], bl[2 * nbj][1],
                               bl[2 * nbj + 1][0], bl[2 * nbj + 1][1],
                               Bb + 8704 + ((klo + b_k) * 136 + wn * 32 + nbj * 16 + b_n) * 2);
                    #pragma unroll
                    for (int mi = 0; mi < 4; ++mi)
                        #pragma unroll
                        for (int nj = 0; nj < 4; ++nj)
                            mma_bf16(acc[mi][nj], ah[mi], bl[nj]);
                }
            }
        }

        if (ch < 7) {
            char* nbuf = smem + (buf ^ 1) * BUF_BYTES;
            #pragma unroll
            for (int it = 0; it < 4; ++it) {
                const int k = sk + it * 8;
                const float4 v = areg[it];
                __nv_bfloat162 h01 = __floats2bfloat162_rn(v.x, v.y);
                __nv_bfloat162 h23 = __floats2bfloat162_rn(v.z, v.w);
                float2 f01 = __bfloat1622float2(h01);
                float2 f23 = __bfloat1622float2(h23);
                __nv_bfloat162 l01 = __floats2bfloat162_rn(v.x - f01.x, v.y - f01.y);
                __nv_bfloat162 l23 = __floats2bfloat162_rn(v.z - f23.x, v.w - f23.y);
                char* ph = nbuf + (size_t)k * 272 + sm * 2;
                *(__nv_bfloat162*)(ph)     = h01;
                *(__nv_bfloat162*)(ph + 4) = h23;
                char* pl = ph + 8704;
                *(__nv_bfloat162*)(pl)     = l01;
                *(__nv_bfloat162*)(pl + 4) = l23;
            }
        }
        CP_WAIT0();
        __syncthreads();
        buf ^= 1;
    }

    // ================= epilogue ============================================
    const int r0 = lane >> 2;
    const int c2 = (lane & 3) * 2;
    #pragma unroll
    for (int mi = 0; mi < 4; ++mi) {
        const int mA = wm * 64 + mi * 16 + r0;            // rows mA, mA+8 (same group)
        const size_t rowbase = (g0 + (size_t)(mA >> 6)) * 16384 + (mA & 63);
        #pragma unroll
        for (int nj = 0; nj < 4; ++nj) {
            const int col = bcol0 + wn * 32 + nj * 8 + c2;
            const float b0 = bias ? __ldg(bias + col)     : 0.f;
            const float b1 = bias ? __ldg(bias + col + 1) : 0.f;
            float* p = C + rowbase + (size_t)col * 64;
            p[0]      = acc[mi][nj][0] + b0;
            p[64]     = acc[mi][nj][1] + b1;
            p[8]      = acc[mi][nj][2] + b0;
            p[64 + 8] = acc[mi][nj][3] + b1;
        }
    }
}

// ---------------- attention: per (pixel, head), softmax over 8 agents -------
__global__ void __launch_bounds__(256)
attn_kernel(const float* __restrict__ qe, const float* __restrict__ ko,
            const float* __restrict__ vo, float* __restrict__ oe)
{
    const int ge = blockIdx.x >> 1;              // b*32 + k
    const int b  = ge >> 5;
    const int k  = ge & 31;
    const int h  = ((blockIdx.x & 1) << 2) + (threadIdx.x >> 6);
    const int n  = threadIdx.x & 63;
    const float scale = 0.1767766952966369f;     // 32^-0.5

    const float* qp = qe + ((size_t)ge * 256 + h * 32) * 64 + n;
    float q[32];
    #pragma unroll
    for (int d = 0; d < 32; ++d) q[d] = qp[d * 64];

    float logit[8];
    #pragma unroll
    for (int j = 0; j < 8; ++j) {
        const size_t go = (size_t)(b * 8 + j) * 32 + k;
        const float* kp = ko + (go * 256 + h * 32) * 64 + n;
        float s = 0.f;
        #pragma unroll
        for (int d = 0; d < 32; ++d) s += q[d] * kp[d * 64];
        logit[j] = s * scale;
    }

    float m = logit[0];
    #pragma unroll
    for (int j = 1; j < 8; ++j) m = fmaxf(m, logit[j]);
    float denom = 0.f;
    #pragma unroll
    for (int j = 0; j < 8; ++j) { logit[j] = expf(logit[j] - m); denom += logit[j]; }
    const float inv = 1.f / denom;

    float o[32];
    #pragma unroll
    for (int d = 0; d < 32; ++d) o[d] = 0.f;
    #pragma unroll
    for (int j = 0; j < 8; ++j) {
        const float a = logit[j] * inv;
        const float* vp = vo + ((size_t)(b * 8 + j) * 32 + k) * 16384 + (h * 32) * 64 + n;
        #pragma unroll
        for (int d = 0; d < 32; ++d) o[d] += a * vp[d * 64];
    }

    float* op = oe + ((size_t)ge * 256 + h * 32) * 64 + n;
    #pragma unroll
    for (int d = 0; d < 32; ++d) op[d * 64] = o[d];
}

// ---------------- out_o broadcast over L ------------------------------------
__global__ void __launch_bounds__(256)
bcast_oo(const float* __restrict__ oo, float* __restrict__ outO)
{
    const int ge = blockIdx.x;
    const int b  = ge >> 5;
    const int k  = ge & 31;
    const float4* src = (const float4*)(oo + (size_t)ge * 16384);
    float4* dst[8];
    #pragma unroll
    for (int l = 0; l < 8; ++l)
        dst[l] = (float4*)(outO + (size_t)((b * 8 + l) * 32 + k) * 16384);
    for (int i = threadIdx.x; i < 4096; i += 256) {
        const float4 v = src[i];
        #pragma unroll
        for (int l = 0; l < 8; ++l) dst[l][i] = v;
    }
}

// ---------------- launcher ---------------------------------------------------
extern "C" void kernel_launch(void* const* d_in, const int* in_sizes, int n_in,
                              void* d_out, int out_size)
{
    const float* ego    = (const float*)d_in[0];
    const float* oth    = (const float*)d_in[1];
    const float* Wqkv_e = (const float*)d_in[2];
    const float* Wqkv_o = (const float*)d_in[3];
    const float* Wout_e = (const float*)d_in[4];
    const float* bout_e = (const float*)d_in[5];
    const float* Wout_o = (const float*)d_in[6];
    const float* bout_o = (const float*)d_in[7];

    float* outE = (float*)d_out;
    float* outO = outE + 16384ull * 256;

    float *qe, *oo, *oe, *ko, *vo, *Co;
    unsigned short *wq_h, *wq_l, *wk_h, *wk_l, *wv_h, *wv_l, *we_h, *we_l, *co_h, *co_l;
    cudaGetSymbolAddress((void**)&qe, g_qe);
    cudaGetSymbolAddress((void**)&oo, g_oo);
    cudaGetSymbolAddress((void**)&oe, g_oe);
    cudaGetSymbolAddress((void**)&ko, g_ko);
    cudaGetSymbolAddress((void**)&vo, g_vo);
    cudaGetSymbolAddress((void**)&Co, g_Co);
    cudaGetSymbolAddress((void**)&wq_h, g_wq_h); cudaGetSymbolAddress((void**)&wq_l, g_wq_l);
    cudaGetSymbolAddress((void**)&wk_h, g_wk_h); cudaGetSymbolAddress((void**)&wk_l, g_wk_l);
    cudaGetSymbolAddress((void**)&wv_h, g_wv_h); cudaGetSymbolAddress((void**)&wv_l, g_wv_l);
    cudaGetSymbolAddress((void**)&we_h, g_we_h); cudaGetSymbolAddress((void**)&we_l, g_we_l);
    cudaGetSymbolAddress((void**)&co_h, g_co_h); cudaGetSymbolAddress((void**)&co_l, g_co_l);

    cudaFuncSetAttribute(bf16_gemm, cudaFuncAttributeMaxDynamicSharedMemorySize,
                         GEMM_SMEM);

    // ---- weight prep
    wsplit<<<256, 256>>>(Wqkv_e, 768, 0,   wq_h, wq_l);
    wsplit<<<256, 256>>>(Wqkv_o, 768, 256, wk_h, wk_l);
    wsplit<<<256, 256>>>(Wqkv_o, 768, 512, wv_h, wv_l);
    wsplit<<<256, 256>>>(Wout_e, 256, 0,   we_h, we_l);
    compute_Co<<<256, 256>>>(Wqkv_e, Wout_o, Co);
    wsplit<<<256, 256>>>(Co, 256, 0, co_h, co_l);

    // ---- projections (tensor cores via mma.sync)
    bf16_gemm<<<dim3(1024, 2), 256, GEMM_SMEM>>>(oth, wk_h, wk_l, ko, nullptr);
    bf16_gemm<<<dim3(1024, 2), 256, GEMM_SMEM>>>(oth, wv_h, wv_l, vo, nullptr);
    bf16_gemm<<<dim3(128, 2),  256, GEMM_SMEM>>>(ego, wq_h, wq_l, qe, nullptr);
    bf16_gemm<<<dim3(128, 2),  256, GEMM_SMEM>>>(ego, co_h, co_l, oo, bout_o);

    // ---- attention + output projection
    attn_kernel<<<512, 256>>>(qe, ko, vo, oe);
    bf16_gemm<<<dim3(128, 2), 256, GEMM_SMEM>>>(oe, we_h, we_l, outE, bout_e);

    // ---- out_o broadcast
    bcast_oo<<<256, 256>>>(oo, outO);
}